// round 1
// baseline (speedup 1.0000x reference)
#include <cuda_runtime.h>

// LinearAttention fused pipeline, fp32 SIMT baseline.
// Shapes fixed by the problem: b=4, X=Y=Z=32 (n=32768/batch), DIM=128,
// HEADS=4, DIM_HEAD=32, qkv width 384.

#define NB        4
#define TOK_PER_B 32768
#define TTOT      (NB * TOK_PER_B)      // 131072 tokens
#define CDIM      128
#define NQKV      384
#define NHEAD     4
#define DHEAD     32

#define MTA       64                    // tokens per block, kernel A
#define NBLKA     (TTOT / MTA)          // 2048
#define BLKPB     (TOK_PER_B / MTA)     // 512 A-blocks per batch
#define PART_STRIDE 4224                // 128*32 P-entries + 128 S-entries

#define MTC       64                    // tokens per block, kernel C
#define NBLKC     (TTOT / MTC)          // 2048

// Scratch (allocation rules forbid cudaMalloc; __device__ globals are the workaround)
__device__ float g_qprime[(size_t)TTOT * CDIM];          // 64 MB: softmaxed q * scale, token-major
__device__ float g_part[(size_t)NBLKA * PART_STRIDE];    // 33 MB: per-block exp(k) x v partials + S
__device__ float g_ctx[NB * NHEAD * DHEAD * DHEAD];      // context[b][h][d][c]
__device__ float g_wcomb[NB * CDIM * CDIM];              // Wcomb[b][hd][c] = ctx_blockdiag @ w_out

// ---------------------------------------------------------------------------
// Kernel A: qkv GEMM (64 tokens x 384 x K=128) + epilogues.
//  - q cols (0..127): per-(token,head) softmax over 32 channels, * DIM_HEAD^-0.5 -> g_qprime
//  - k cols (128..255): exp in place
//  - v cols (256..383): P[h][d][c] = sum_t ek[t][h][d] * v[t][h][c]; S[hd] = sum_t ek
//    written as per-block partials to g_part (reduced in kernel B).
// 512 threads; per-thread tile 4 tokens x 12 cols (48 accs).
// ---------------------------------------------------------------------------
__global__ __launch_bounds__(512, 1)
void kA(const float* __restrict__ x, const float* __restrict__ wqkv)
{
    extern __shared__ float sm[];
    float* xs = sm;                 // [64][36]  (pad 36 keeps float4 stores aligned)
    float* ws = sm + MTA * 36;      // [32][384] K-chunk of w_qkv

    const int tid = threadIdx.x;
    const int t0  = blockIdx.x * MTA;
    const int mg  = tid >> 5;       // 0..15  (token group)
    const int ng  = tid & 31;       // 0..31  (col group)
    const int m0  = mg * 4;
    const int n0  = ng * 12;

    float acc[4][12];
#pragma unroll
    for (int i = 0; i < 4; ++i)
#pragma unroll
        for (int j = 0; j < 12; ++j) acc[i][j] = 0.f;

    const int xr  = tid >> 3;        // 0..63
    const int xc4 = (tid & 7) * 4;   // 0..28

    for (int kc = 0; kc < 4; ++kc) {
        __syncthreads();
        // load x tile [64 tokens][32 k] (coalesced float4, row-major -> xs[r][c])
        {
            float4 v = *(const float4*)&x[(size_t)(t0 + xr) * CDIM + kc * 32 + xc4];
            *(float4*)&xs[xr * 36 + xc4] = v;
        }
        // load w chunk: rows kc*32..+31, all 384 cols == 12288 contiguous floats
        {
            const float4* src = (const float4*)&wqkv[(size_t)kc * 32 * NQKV];
            float4* dst = (float4*)ws;
#pragma unroll
            for (int i = 0; i < 6; ++i) dst[tid + 512 * i] = src[tid + 512 * i];
        }
        __syncthreads();

#pragma unroll 4
        for (int k = 0; k < 32; ++k) {
            float a_[4];
#pragma unroll
            for (int i = 0; i < 4; ++i) a_[i] = xs[(m0 + i) * 36 + k];  // warp-uniform -> broadcast
            const float* wr = &ws[k * NQKV + n0];
            float4 w0 = *(const float4*)(wr);
            float4 w1 = *(const float4*)(wr + 4);
            float4 w2 = *(const float4*)(wr + 8);
            float b_[12] = { w0.x, w0.y, w0.z, w0.w, w1.x, w1.y, w1.z, w1.w,
                             w2.x, w2.y, w2.z, w2.w };
#pragma unroll
            for (int i = 0; i < 4; ++i)
#pragma unroll
                for (int j = 0; j < 12; ++j)
                    acc[i][j] = fmaf(a_[i], b_[j], acc[i][j]);
        }
    }

    // ---- epilogue: stage full 64x384 tile in smem (aliases xs/ws) ----
    __syncthreads();
    float* qs = sm;                 // [64][388]
#pragma unroll
    for (int i = 0; i < 4; ++i)
#pragma unroll
        for (int j = 0; j < 12; ++j)
            qs[(m0 + i) * 388 + n0 + j] = acc[i][j];
    __syncthreads();

    // q softmax over 32 channels per (token, head); fold * DIM_HEAD^-0.5
    if (tid < 256) {
        const int t = tid >> 2, h = tid & 3;
        float* row = &qs[t * 388 + h * 32];
        float m = row[0];
#pragma unroll
        for (int d = 1; d < DHEAD; ++d) m = fmaxf(m, row[d]);
        float s = 0.f;
#pragma unroll
        for (int d = 0; d < DHEAD; ++d) { float e = expf(row[d] - m); row[d] = e; s += e; }
        const float inv = 0.17677669529663687f / s;   // scale / sum
#pragma unroll
        for (int d = 0; d < DHEAD; ++d) row[d] *= inv;
    }
    __syncthreads();

    // coalesced copy of q' (cols 0..127) to gmem
    {
        float4* dst = (float4*)&g_qprime[(size_t)t0 * CDIM];
        for (int i = tid; i < MTA * 32; i += 512) {
            const int r = i >> 5, c4 = i & 31;
            dst[r * 32 + c4] = *(float4*)&qs[r * 388 + c4 * 4];
        }
    }
    // exp(k) in place (cols 128..255); safe without max-sub: |k| small, denom handled in kB
    for (int i = tid; i < MTA * CDIM; i += 512) {
        const int t = i >> 7, hd = i & 127;
        float* p = &qs[t * 388 + 128 + hd];
        *p = expf(*p);
    }
    __syncthreads();

    // P[hd][c-octet] + S partials over the 64 tokens of this block
    {
        const int hd = tid >> 2;          // 0..127
        const int cg = tid & 3;           // c-octet
        const int h  = hd >> 5;
        float P[8] = {0, 0, 0, 0, 0, 0, 0, 0};
        float S = 0.f;
        for (int t = 0; t < MTA; ++t) {
            const float e = qs[t * 388 + 128 + hd];
            const float4* vp = (const float4*)&qs[t * 388 + 256 + h * 32 + cg * 8];
            const float4 v0 = vp[0], v1 = vp[1];
            P[0] = fmaf(e, v0.x, P[0]); P[1] = fmaf(e, v0.y, P[1]);
            P[2] = fmaf(e, v0.z, P[2]); P[3] = fmaf(e, v0.w, P[3]);
            P[4] = fmaf(e, v1.x, P[4]); P[5] = fmaf(e, v1.y, P[5]);
            P[6] = fmaf(e, v1.z, P[6]); P[7] = fmaf(e, v1.w, P[7]);
            S += e;
        }
        float* out = &g_part[(size_t)blockIdx.x * PART_STRIDE];
#pragma unroll
        for (int j = 0; j < 8; ++j) out[hd * 32 + cg * 8 + j] = P[j];
        if (cg == 0) out[4096 + hd] = S;
    }
}

// ---------------------------------------------------------------------------
// Kernel B: reduce per-block partials -> context[b][h][d][c] = P/S
// grid 64 = (b, h, c-slice of 8); 256 threads, one (d,c) output each.
// ---------------------------------------------------------------------------
__global__ void kB()
{
    __shared__ float Ss[DHEAD];
    const int b  = blockIdx.x >> 4;
    const int h  = (blockIdx.x >> 2) & 3;
    const int cs = blockIdx.x & 3;
    const int d  = threadIdx.x >> 3;
    const int cl = threadIdx.x & 7;
    const int c  = cs * 8 + cl;

    const float* base = g_part + (size_t)b * BLKPB * PART_STRIDE;
    const float* p = base + (h * 32 + d) * 32 + c;

    float a0 = 0, a1 = 0, a2 = 0, a3 = 0, a4 = 0, a5 = 0, a6 = 0, a7 = 0;
    for (int i = 0; i < BLKPB; i += 8) {
        a0 += p[(size_t)(i + 0) * PART_STRIDE]; a1 += p[(size_t)(i + 1) * PART_STRIDE];
        a2 += p[(size_t)(i + 2) * PART_STRIDE]; a3 += p[(size_t)(i + 3) * PART_STRIDE];
        a4 += p[(size_t)(i + 4) * PART_STRIDE]; a5 += p[(size_t)(i + 5) * PART_STRIDE];
        a6 += p[(size_t)(i + 6) * PART_STRIDE]; a7 += p[(size_t)(i + 7) * PART_STRIDE];
    }
    const float acc = ((a0 + a1) + (a2 + a3)) + ((a4 + a5) + (a6 + a7));

    if (cl == 0) {
        const float* ps = base + 4096 + h * 32 + d;
        float s0 = 0, s1 = 0, s2 = 0, s3 = 0;
        for (int i = 0; i < BLKPB; i += 4) {
            s0 += ps[(size_t)(i + 0) * PART_STRIDE]; s1 += ps[(size_t)(i + 1) * PART_STRIDE];
            s2 += ps[(size_t)(i + 2) * PART_STRIDE]; s3 += ps[(size_t)(i + 3) * PART_STRIDE];
        }
        Ss[d] = (s0 + s1) + (s2 + s3);
    }
    __syncthreads();
    g_ctx[((b * NHEAD + h) * DHEAD + d) * DHEAD + c] = acc / Ss[d];
}

// ---------------------------------------------------------------------------
// Kernel B2: Wcomb[b][h*32+d][c] = sum_e ctx[b][h][d][e] * w_out[h*32+e][c]
// grid 16 = (b,h); 256 threads.
// ---------------------------------------------------------------------------
__global__ void kB2(const float* __restrict__ wout)
{
    __shared__ float cs_[DHEAD * DHEAD];   // ctx slice
    __shared__ float wsh[DHEAD * CDIM];    // w_out rows h*32..+31
    const int b = blockIdx.x >> 2, h = blockIdx.x & 3;
    const int tid = threadIdx.x;

    for (int i = tid; i < DHEAD * DHEAD; i += 256)
        cs_[i] = g_ctx[(b * NHEAD + h) * (DHEAD * DHEAD) + i];
    for (int i = tid; i < DHEAD * CDIM; i += 256)
        wsh[i] = wout[(size_t)h * 32 * CDIM + i];
    __syncthreads();

#pragma unroll 1
    for (int r = 0; r < 16; ++r) {
        const int o = tid + 256 * r;
        const int d = o >> 7, c = o & 127;
        float a = 0.f;
#pragma unroll
        for (int e = 0; e < DHEAD; ++e)
            a = fmaf(cs_[d * 32 + e], wsh[e * 128 + c], a);
        g_wcomb[b * (CDIM * CDIM) + (h * 32 + d) * CDIM + c] = a;
    }
}

// ---------------------------------------------------------------------------
// Kernel C: y = q' @ Wcomb[b] + b_out, then LayerNorm(128) -> out.
// 64 tokens/block, 256 threads, per-thread tile 8 tokens x 4 cols.
// ---------------------------------------------------------------------------
__global__ __launch_bounds__(256, 1)
void kC(const float* __restrict__ bout, const float* __restrict__ lns,
        const float* __restrict__ lnb, float* __restrict__ out)
{
    extern __shared__ float sm[];
    float* qs   = sm;                  // [64][132]
    float* wc   = sm + MTC * 132;      // [128][128]
    float* bias = wc + CDIM * CDIM;    // 128
    float* gsc  = bias + CDIM;         // ln scale
    float* gbi  = gsc + CDIM;          // ln bias

    const int tid = threadIdx.x;
    const int t0  = blockIdx.x * MTC;
    const int b   = blockIdx.x >> 9;   // 512 blocks per batch

    {
        const float4* src = (const float4*)&g_qprime[(size_t)t0 * CDIM];
        for (int i = tid; i < MTC * 32; i += 256) {
            const int r = i >> 5, c4 = i & 31;
            *(float4*)&qs[r * 132 + c4 * 4] = src[i];
        }
        const float4* wsrc = (const float4*)&g_wcomb[(size_t)b * CDIM * CDIM];
        for (int i = tid; i < 4096; i += 256) ((float4*)wc)[i] = wsrc[i];
        if (tid < CDIM) { bias[tid] = bout[tid]; gsc[tid] = lns[tid]; gbi[tid] = lnb[tid]; }
    }
    __syncthreads();

    const int mg = tid >> 5;           // 0..7  -> 8 tokens
    const int ng = tid & 31;           // 0..31 -> 4 cols (float4 stride: conflict-free)
    const int m0 = mg * 8, n0 = ng * 4;

    float acc[8][4];
#pragma unroll
    for (int i = 0; i < 8; ++i)
#pragma unroll
        for (int j = 0; j < 4; ++j) acc[i][j] = 0.f;

#pragma unroll 4
    for (int k = 0; k < CDIM; ++k) {
        float a_[8];
#pragma unroll
        for (int i = 0; i < 8; ++i) a_[i] = qs[(m0 + i) * 132 + k];   // broadcast
        const float4 w4 = *(const float4*)&wc[k * CDIM + n0];
#pragma unroll
        for (int i = 0; i < 8; ++i) {
            acc[i][0] = fmaf(a_[i], w4.x, acc[i][0]);
            acc[i][1] = fmaf(a_[i], w4.y, acc[i][1]);
            acc[i][2] = fmaf(a_[i], w4.z, acc[i][2]);
            acc[i][3] = fmaf(a_[i], w4.w, acc[i][3]);
        }
    }

    __syncthreads();                   // done reading qs; reuse as y staging
    float* ys = qs;                    // [64][132]
#pragma unroll
    for (int i = 0; i < 8; ++i)
#pragma unroll
        for (int j = 0; j < 4; ++j)
            ys[(m0 + i) * 132 + n0 + j] = acc[i][j] + bias[n0 + j];
    __syncthreads();

    // LayerNorm: warp per token (8 tokens per warp), two-pass in registers
    const int wid = tid >> 5, lane = tid & 31;
    for (int tt = wid * 8; tt < wid * 8 + 8; ++tt) {
        const float4 v = *(const float4*)&ys[tt * 132 + lane * 4];
        float s = v.x + v.y + v.z + v.w;
#pragma unroll
        for (int off = 16; off; off >>= 1) s += __shfl_xor_sync(0xffffffffu, s, off);
        const float mu = s * (1.f / 128.f);
        const float dx = v.x - mu, dy = v.y - mu, dz = v.z - mu, dw = v.w - mu;
        float q = dx * dx + dy * dy + dz * dz + dw * dw;
#pragma unroll
        for (int off = 16; off; off >>= 1) q += __shfl_xor_sync(0xffffffffu, q, off);
        const float rs = rsqrtf(q * (1.f / 128.f) + 1e-6f);
        const int c = lane * 4;
        const float4 g = *(const float4*)&gsc[c];
        const float4 bb = *(const float4*)&gbi[c];
        float4 o;
        o.x = fmaf(dx * rs, g.x, bb.x);
        o.y = fmaf(dy * rs, g.y, bb.y);
        o.z = fmaf(dz * rs, g.z, bb.z);
        o.w = fmaf(dw * rs, g.w, bb.w);
        *(float4*)&out[(size_t)(t0 + tt) * CDIM + c] = o;
    }
}

// ---------------------------------------------------------------------------
extern "C" void kernel_launch(void* const* d_in, const int* in_sizes, int n_in,
                              void* d_out, int out_size)
{
    (void)in_sizes; (void)n_in; (void)out_size;
    const float* x    = (const float*)d_in[0];
    const float* wqkv = (const float*)d_in[1];
    const float* wout = (const float*)d_in[2];
    const float* bout = (const float*)d_in[3];
    const float* lns  = (const float*)d_in[4];
    const float* lnb  = (const float*)d_in[5];
    float* out = (float*)d_out;

    const int smA = MTA * 388 * 4;                         // 99328 B
    const int smC = (MTC * 132 + CDIM * CDIM + 3 * CDIM) * 4; // 100864 B
    cudaFuncSetAttribute(kA, cudaFuncAttributeMaxDynamicSharedMemorySize, smA);
    cudaFuncSetAttribute(kC, cudaFuncAttributeMaxDynamicSharedMemorySize, smC);

    kA<<<NBLKA, 512, smA>>>(x, wqkv);
    kB<<<64, 256>>>();
    kB2<<<16, 256>>>(wout);
    kC<<<NBLKC, 256, smC>>>(bout, lns, lnb, out);
}